// round 9
// baseline (speedup 1.0000x reference)
#include <cuda_runtime.h>
#include <cuda_bf16.h>

#define DIM 4096
#define DIM4 (DIM / 4)   // 1024 float4s per row
#define UNROLL 4         // weight quads per thread (columns tid + k*256)
#define ROWS_PER_BLK 2
#define TPB 256

// 2 consecutive rows per independent block, 8 front-batched LDG.128s per
// thread (MLP_p1 = 8), weight quads gathered once and shared across both rows
// (same column positions). Non-persistent: R6/R7 showed the grid-stride loop
// carry — not occupancy — caps cross-iteration MLP.
//
// shard_map dtype runtime-detected (int32 vs int64 viewed as int32 pairs):
// shard_map[512] == 1 by construction; an int64 buffer gives arr32[512] == 0.
__global__ void __launch_bounds__(TPB) fused_scale_kernel(
    const float4* __restrict__ x,
    const float4* __restrict__ shards4,   // [num_shards][DIM4]
    const int*    __restrict__ map32,
    float4* __restrict__ out)
{
    const bool is_int64 = (map32[512] == 0);
    const long long base0 = (long long)blockIdx.x * (ROWS_PER_BLK * DIM4) + threadIdx.x;
    const long long base1 = base0 + DIM4;

    // 8 independent streaming loads, front-batched into the L1tex queue.
    float4 xv0[UNROLL], xv1[UNROLL];
#pragma unroll
    for (int k = 0; k < UNROLL; k++)
        xv0[k] = __ldcs(&x[base0 + k * TPB]);
#pragma unroll
    for (int k = 0; k < UNROLL; k++)
        xv1[k] = __ldcs(&x[base1 + k * TPB]);

    // L2-hot weight gather (shared by both rows) overlaps the DRAM latency.
    float4 wv[UNROLL];
#pragma unroll
    for (int k = 0; k < UNROLL; k++) {
        int d4 = threadIdx.x + k * TPB;   // float4 index within row
        int d  = d4 * 4;                  // first dim of this quad
        int s  = is_int64 ? __ldg(&map32[2 * d]) : __ldg(&map32[d]);
        wv[k] = __ldg(&shards4[(long long)s * DIM4 + d4]);
    }

#pragma unroll
    for (int k = 0; k < UNROLL; k++) {
        float4 o;
        o.x = xv0[k].x * wv[k].x;
        o.y = xv0[k].y * wv[k].y;
        o.z = xv0[k].z * wv[k].z;
        o.w = xv0[k].w * wv[k].w;
        __stcs(&out[base0 + k * TPB], o);
    }
#pragma unroll
    for (int k = 0; k < UNROLL; k++) {
        float4 o;
        o.x = xv1[k].x * wv[k].x;
        o.y = xv1[k].y * wv[k].y;
        o.z = xv1[k].z * wv[k].z;
        o.w = xv1[k].w * wv[k].w;
        __stcs(&out[base1 + k * TPB], o);
    }
}

extern "C" void kernel_launch(void* const* d_in, const int* in_sizes, int n_in,
                              void* d_out, int out_size) {
    const float* x      = (const float*)d_in[0];
    const float* shards = (const float*)d_in[1];
    const int*   map32  = (const int*)d_in[2];   // int32 view; kernel decodes
    float* out = (float*)d_out;

    long long n      = (long long)in_sizes[0];   // total elements of x
    long long nrows  = n / DIM;                  // 16384 rows
    long long nblks  = nrows / ROWS_PER_BLK;     // 8192 blocks

    fused_scale_kernel<<<(unsigned)nblks, TPB>>>(
        reinterpret_cast<const float4*>(x),
        reinterpret_cast<const float4*>(shards),
        map32,
        reinterpret_cast<float4*>(out));
}

// round 10
// speedup vs baseline: 1.0039x; 1.0039x over previous
#include <cuda_runtime.h>
#include <cuda_bf16.h>

#define DIM 4096
#define DIM4 (DIM / 4)   // 1024 float4s per row
#define UNROLL 4
#define TPB 256

// FINAL (converged): one independent block per DIM row, 4 front-batched
// LDG.128s per thread, weights gathered on the fly from the L2-resident
// map (16 KB) + shards (128 KB) tables, streaming cache hints on the
// x/out DRAM stream.
//
// Convergence evidence (kernel-time / DRAM%):
//   this structure:            76.06-76.22us / 80.1%  <- best
//   2 rows/blk (MLP_p1=8):     76.61us / 79.5%        (tie: supply not limiting)
//   persistent grid-stride:    82.0us  / 74.6%        (loop carry caps MLP)
// DRAM% is invariant at ~80% across occ 62-83% and MLP 4-8 => the balanced
// 256MB-read + 256MB-write HBM mix is bound at ~6.35 TB/s (HW ceiling for
// read/write turnaround), so the kernel is at the roofline.
//
// shard_map dtype runtime-detected (int32 vs int64 viewed as int32 pairs):
// shard_map[512] == 1 by construction; an int64 buffer gives arr32[512] == 0.
__global__ void __launch_bounds__(TPB, 8) fused_scale_kernel(
    const float4* __restrict__ x,
    const float4* __restrict__ shards4,   // [num_shards][DIM4]
    const int*    __restrict__ map32,
    float4* __restrict__ out)
{
    const bool is_int64 = (map32[512] == 0);
    const long long base = (long long)blockIdx.x * DIM4 + threadIdx.x;

    // Streaming x loads first: DRAM requests enter the L1tex queue
    // immediately, 4 independent LDG.128s (MLP_p1 = 4).
    float4 xv[UNROLL];
#pragma unroll
    for (int k = 0; k < UNROLL; k++)
        xv[k] = __ldcs(&x[base + k * TPB]);

    // L2-hot weight gather overlaps the DRAM latency above.
    float4 wv[UNROLL];
#pragma unroll
    for (int k = 0; k < UNROLL; k++) {
        int d4 = threadIdx.x + k * TPB;   // float4 index within row
        int d  = d4 * 4;                  // first dim of this quad
        int s  = is_int64 ? __ldg(&map32[2 * d]) : __ldg(&map32[d]);
        wv[k] = __ldg(&shards4[(long long)s * DIM4 + d4]);
    }

#pragma unroll
    for (int k = 0; k < UNROLL; k++) {
        float4 o;
        o.x = xv[k].x * wv[k].x;
        o.y = xv[k].y * wv[k].y;
        o.z = xv[k].z * wv[k].z;
        o.w = xv[k].w * wv[k].w;
        __stcs(&out[base + k * TPB], o);
    }
}

extern "C" void kernel_launch(void* const* d_in, const int* in_sizes, int n_in,
                              void* d_out, int out_size) {
    const float* x      = (const float*)d_in[0];
    const float* shards = (const float*)d_in[1];
    const int*   map32  = (const int*)d_in[2];   // int32 view; kernel decodes
    float* out = (float*)d_out;

    long long n     = (long long)in_sizes[0];    // total elements of x
    long long nrows = n / DIM;                   // 16384 rows

    fused_scale_kernel<<<(unsigned)nrows, TPB>>>(
        reinterpret_cast<const float4*>(x),
        reinterpret_cast<const float4*>(shards),
        map32,
        reinterpret_cast<float4*>(out));
}

// round 11
// speedup vs baseline: 1.0047x; 1.0008x over previous
#include <cuda_runtime.h>
#include <cuda_bf16.h>

#define DIM 4096
#define DIM4 (DIM / 4)   // 1024 float4s per row
#define UNROLL 4
#define TPB 256

// FINAL (converged, 3x reproduced at 75.8-76.2us kernel / 80% DRAM):
// one independent block per DIM row, 4 front-batched LDG.128s per thread,
// weights gathered on the fly from the L2-resident map (16 KB) + shards
// (128 KB) tables, streaming cache hints on the x/out DRAM stream.
//
// Convergence evidence (kernel-time / DRAM%):
//   this structure:            75.78-76.22us / 80.1-80.5%  <- best
//   2 rows/blk (MLP_p1=8):     76.61us / 79.5%   (tie: supply not limiting)
//   persistent grid-stride:    82.0us  / 74.6%   (loop carry caps MLP)
// DRAM% invariant across occ 46-84% and MLP 4-8 => the balanced 256MB-read
// + 256MB-write HBM mix is bound at ~6.38 TB/s (read/write-turnaround
// ceiling); the kernel is at the roofline.
//
// shard_map dtype runtime-detected (int32 vs int64 viewed as int32 pairs):
// shard_map[512] == 1 by construction; an int64 buffer gives arr32[512] == 0.
__global__ void __launch_bounds__(TPB, 8) fused_scale_kernel(
    const float4* __restrict__ x,
    const float4* __restrict__ shards4,   // [num_shards][DIM4]
    const int*    __restrict__ map32,
    float4* __restrict__ out)
{
    const bool is_int64 = (map32[512] == 0);
    const long long base = (long long)blockIdx.x * DIM4 + threadIdx.x;

    // Streaming x loads first: DRAM requests enter the L1tex queue
    // immediately, 4 independent LDG.128s (MLP_p1 = 4).
    float4 xv[UNROLL];
#pragma unroll
    for (int k = 0; k < UNROLL; k++)
        xv[k] = __ldcs(&x[base + k * TPB]);

    // L2-hot weight gather overlaps the DRAM latency above.
    float4 wv[UNROLL];
#pragma unroll
    for (int k = 0; k < UNROLL; k++) {
        int d4 = threadIdx.x + k * TPB;   // float4 index within row
        int d  = d4 * 4;                  // first dim of this quad
        int s  = is_int64 ? __ldg(&map32[2 * d]) : __ldg(&map32[d]);
        wv[k] = __ldg(&shards4[(long long)s * DIM4 + d4]);
    }

#pragma unroll
    for (int k = 0; k < UNROLL; k++) {
        float4 o;
        o.x = xv[k].x * wv[k].x;
        o.y = xv[k].y * wv[k].y;
        o.z = xv[k].z * wv[k].z;
        o.w = xv[k].w * wv[k].w;
        __stcs(&out[base + k * TPB], o);
    }
}

extern "C" void kernel_launch(void* const* d_in, const int* in_sizes, int n_in,
                              void* d_out, int out_size) {
    const float* x      = (const float*)d_in[0];
    const float* shards = (const float*)d_in[1];
    const int*   map32  = (const int*)d_in[2];   // int32 view; kernel decodes
    float* out = (float*)d_out;

    long long n     = (long long)in_sizes[0];    // total elements of x
    long long nrows = n / DIM;                   // 16384 rows

    fused_scale_kernel<<<(unsigned)nrows, TPB>>>(
        reinterpret_cast<const float4*>(x),
        reinterpret_cast<const float4*>(shards),
        map32,
        reinterpret_cast<float4*>(out));
}

// round 12
// speedup vs baseline: 1.0051x; 1.0004x over previous
#include <cuda_runtime.h>
#include <cuda_bf16.h>

#define DIM 4096
#define DIM4 (DIM / 4)   // 1024 float4s per row
#define UNROLL 4
#define TPB 256

// FINAL (converged; 4x reproduced at 75.8-76.3us kernel / 80% DRAM):
// one independent block per DIM row, 4 front-batched LDG.128s per thread,
// weights gathered on the fly from the L2-resident map (16 KB) + shards
// (128 KB) tables, streaming cache hints on the x/out DRAM stream.
//
// Convergence evidence (kernel-time / DRAM%):
//   this structure:            75.78-76.26us / 80.0-80.5%  <- best, at roofline
//   2 rows/blk (MLP_p1=8):     76.61us / 79.5%   (tie: request supply not limiting)
//   persistent grid-stride:    82.0us  / 74.6%   (loop carry caps MLP)
// DRAM% invariant across occ 46-84% and MLP 4-8 => the balanced 256MB-read
// + 256MB-write HBM mix is bound at ~6.35 TB/s (read/write-turnaround
// ceiling; LTS cap is path-independent so TMA/256b variants cannot beat it).
//
// shard_map dtype runtime-detected (int32 vs int64 viewed as int32 pairs):
// shard_map[512] == 1 by construction; an int64 buffer gives arr32[512] == 0.
__global__ void __launch_bounds__(TPB, 8) fused_scale_kernel(
    const float4* __restrict__ x,
    const float4* __restrict__ shards4,   // [num_shards][DIM4]
    const int*    __restrict__ map32,
    float4* __restrict__ out)
{
    const bool is_int64 = (map32[512] == 0);
    const long long base = (long long)blockIdx.x * DIM4 + threadIdx.x;

    // Streaming x loads first: DRAM requests enter the L1tex queue
    // immediately, 4 independent LDG.128s (MLP_p1 = 4).
    float4 xv[UNROLL];
#pragma unroll
    for (int k = 0; k < UNROLL; k++)
        xv[k] = __ldcs(&x[base + k * TPB]);

    // L2-hot weight gather overlaps the DRAM latency above.
    float4 wv[UNROLL];
#pragma unroll
    for (int k = 0; k < UNROLL; k++) {
        int d4 = threadIdx.x + k * TPB;   // float4 index within row
        int d  = d4 * 4;                  // first dim of this quad
        int s  = is_int64 ? __ldg(&map32[2 * d]) : __ldg(&map32[d]);
        wv[k] = __ldg(&shards4[(long long)s * DIM4 + d4]);
    }

#pragma unroll
    for (int k = 0; k < UNROLL; k++) {
        float4 o;
        o.x = xv[k].x * wv[k].x;
        o.y = xv[k].y * wv[k].y;
        o.z = xv[k].z * wv[k].z;
        o.w = xv[k].w * wv[k].w;
        __stcs(&out[base + k * TPB], o);
    }
}

extern "C" void kernel_launch(void* const* d_in, const int* in_sizes, int n_in,
                              void* d_out, int out_size) {
    const float* x      = (const float*)d_in[0];
    const float* shards = (const float*)d_in[1];
    const int*   map32  = (const int*)d_in[2];   // int32 view; kernel decodes
    float* out = (float*)d_out;

    long long n     = (long long)in_sizes[0];    // total elements of x
    long long nrows = n / DIM;                   // 16384 rows

    fused_scale_kernel<<<(unsigned)nrows, TPB>>>(
        reinterpret_cast<const float4*>(x),
        reinterpret_cast<const float4*>(shards),
        map32,
        reinterpret_cast<float4*>(out));
}